// round 3
// baseline (speedup 1.0000x reference)
#include <cuda_runtime.h>

#define CHUNKS 37
#define TPB 256
#define DBLKS 2            // column blocks in partial kernel (2048 cols each)
#define FBLK 8             // column blocks in finalize kernel (512 cols each)
#define FTPB 128

// Scratch: partial sums [B, CHUNKS, D]. 16 MB static (needs 9.7 MB here).
__device__ float g_partial[1 << 22];
__device__ float g_ss[64 * FBLK];      // per-(b, colblock) squared-norm partials
__device__ int   g_cnt[64];            // per-b arrival counters (reset by k1)

// ---------------------------------------------------------------------------
// Kernel 1: per-(sequence, token-chunk, column-slice) partial sums.
// grid = (B, CHUNKS, DBLKS) = 16*37*2 = 1184 = 148 SMs * 8 blocks:
// exactly one balanced wave at 8 blocks/SM (launch_bounds caps regs at 32).
// ---------------------------------------------------------------------------
__global__ void __launch_bounds__(TPB, 8) pool_partial_kernel(
    const float* __restrict__ hs,
    const int* __restrict__ plens,
    const int* __restrict__ ilens,
    int D)
{
    // Reset finalize counters for this replay (graph-safe: k2 runs after k1).
    if (blockIdx.x == 0 && blockIdx.y == 0 && blockIdx.z == 0 &&
        threadIdx.x < 64)
        g_cnt[threadIdx.x] = 0;

    const int b     = blockIdx.x;
    const int chunk = blockIdx.y;
    const int dblk  = blockIdx.z;

    long start = 0;
    for (int i = 0; i < b; ++i) start += plens[i];

    const int pl = plens[b];
    const int il = ilens[b];
    const int n  = pl - il;  // valid token count

    const int t0 = (int)((long)chunk * n / CHUNKS);
    const int t1 = (int)((long)(chunk + 1) * n / CHUNKS);

    // Two float4 column slots per thread, 1024 cols apart (both coalesced).
    const int col_a = dblk * (TPB * 8) + threadIdx.x * 4;
    const int col_b = col_a + TPB * 4;
    if (col_a >= D) return;
    const bool hasB = (col_b < D);

    const float* base = hs + (start + il) * (long)D + col_a;

    float4 accA = make_float4(0.f, 0.f, 0.f, 0.f);
    float4 accB = make_float4(0.f, 0.f, 0.f, 0.f);

    int t = t0;
    for (; t + 2 <= t1; t += 2) {
        const float* p0 = base + (long)t * D;
        const float* p1 = base + (long)(t + 1) * D;
        float4 v0a = __ldcs((const float4*)p0);
        float4 v1a = __ldcs((const float4*)p1);
        if (hasB) {
            float4 v0b = __ldcs((const float4*)(p0 + TPB * 4));
            float4 v1b = __ldcs((const float4*)(p1 + TPB * 4));
            accB.x += v0b.x + v1b.x; accB.y += v0b.y + v1b.y;
            accB.z += v0b.z + v1b.z; accB.w += v0b.w + v1b.w;
        }
        accA.x += v0a.x + v1a.x; accA.y += v0a.y + v1a.y;
        accA.z += v0a.z + v1a.z; accA.w += v0a.w + v1a.w;
    }
    for (; t < t1; ++t) {
        const float* p0 = base + (long)t * D;
        float4 v0a = __ldcs((const float4*)p0);
        accA.x += v0a.x; accA.y += v0a.y; accA.z += v0a.z; accA.w += v0a.w;
        if (hasB) {
            float4 v0b = __ldcs((const float4*)(p0 + TPB * 4));
            accB.x += v0b.x; accB.y += v0b.y; accB.z += v0b.z; accB.w += v0b.w;
        }
    }

    float* out = g_partial + ((long)b * CHUNKS + chunk) * D;
    *(float4*)(out + col_a) = accA;
    if (hasB) *(float4*)(out + col_b) = accB;
}

// ---------------------------------------------------------------------------
// Kernel 2: reduce chunks -> mean (kept in registers), grid-sync via spin on
// a per-sequence counter, deterministic norm, normalize, write output.
// grid = (B, FBLK) = 128 blocks <= 148 SMs -> all co-resident, spin is safe.
// ---------------------------------------------------------------------------
__global__ void __launch_bounds__(FTPB) pool_finalize_kernel(
    const int* __restrict__ plens,
    const int* __restrict__ ilens,
    float* __restrict__ out,
    int D)
{
    const int b    = blockIdx.x;
    const int cblk = blockIdx.y;
    const int cnt  = plens[b] - ilens[b];
    const float inv = 1.0f / (float)cnt;

    const int col = cblk * (FTPB * 4) + threadIdx.x * 4;

    float4 mean = make_float4(0.f, 0.f, 0.f, 0.f);
    float ss_local = 0.f;

    if (col < D) {
        const float* pb = g_partial + (long)b * CHUNKS * D + col;
        #pragma unroll
        for (int ch = 0; ch < CHUNKS; ++ch) {
            float4 v = __ldg((const float4*)(pb + (long)ch * D));
            mean.x += v.x; mean.y += v.y; mean.z += v.z; mean.w += v.w;
        }
        mean.x *= inv; mean.y *= inv; mean.z *= inv; mean.w *= inv;
        ss_local = mean.x * mean.x + mean.y * mean.y +
                   mean.z * mean.z + mean.w * mean.w;
    }

    // Block reduction of ss_local (4 warps).
    __shared__ float red[FTPB / 32];
    unsigned mask = 0xFFFFFFFFu;
    float ss = ss_local;
    #pragma unroll
    for (int off = 16; off > 0; off >>= 1)
        ss += __shfl_xor_sync(mask, ss, off);
    const int lane = threadIdx.x & 31;
    const int wid  = threadIdx.x >> 5;
    if (lane == 0) red[wid] = ss;
    __syncthreads();
    if (threadIdx.x == 0) {
        float v = red[0] + red[1] + red[2] + red[3];
        g_ss[b * FBLK + cblk] = v;
        __threadfence();
        atomicAdd(&g_cnt[b], 1);
        // Spin until all FBLK blocks of this sequence have arrived.
        while (*(volatile int*)&g_cnt[b] < FBLK) { }
    }
    __syncthreads();

    // Deterministic fixed-order sum of the FBLK partials.
    float total = 0.f;
    #pragma unroll
    for (int i = 0; i < FBLK; ++i)
        total += *(volatile float*)&g_ss[b * FBLK + i];

    float norm = fmaxf(sqrtf(total), 1e-12f);
    const float r = 1.0f / norm;

    if (col < D) {
        mean.x *= r; mean.y *= r; mean.z *= r; mean.w *= r;
        *(float4*)(out + (long)b * D + col) = mean;
    }
}

// ---------------------------------------------------------------------------
extern "C" void kernel_launch(void* const* d_in, const int* in_sizes, int n_in,
                              void* d_out, int out_size)
{
    const float* hs    = (const float*)d_in[0];
    const int*   plens = (const int*)d_in[1];
    const int*   ilens = (const int*)d_in[2];
    float*       out   = (float*)d_out;

    const int B = in_sizes[1];
    const int D = out_size / B;

    const int dblocks = (D + TPB * 8 - 1) / (TPB * 8);   // 2048 cols per block

    dim3 grid1(B, CHUNKS, dblocks);
    pool_partial_kernel<<<grid1, TPB>>>(hs, plens, ilens, D);

    const int fblocks = (D + FTPB * 4 - 1) / (FTPB * 4); // 512 cols per block
    dim3 grid2(B, fblocks);
    pool_finalize_kernel<<<grid2, FTPB>>>(plens, ilens, out, D);
}

// round 4
// speedup vs baseline: 1.0418x; 1.0418x over previous
#include <cuda_runtime.h>

#define CHUNKS 16
#define TPB 256
#define FBLK 8             // column blocks in finalize kernel (512 cols each)
#define FTPB 128

// Scratch: partial sums [B, CHUNKS, D]. 16 MB static (needs 4 MB here).
__device__ float g_partial[1 << 22];
__device__ float g_ss[64 * FBLK];      // per-(b, colblock) squared-norm partials
__device__ int   g_cnt[64];            // per-b arrival counters (reset by k1)

// ---------------------------------------------------------------------------
// Kernel 1: per-(sequence, token-chunk, column-slice) partial sums.
// grid = (B, CHUNKS, D/1024) = 16*16*4 = 1024 blocks -> ~6.9 blocks/SM,
// launch_bounds(256,7) forces 7 co-resident -> 98.8% last-wave utilization.
// 4-deep token unroll keeps >=28KB/SM of loads in flight (latency covered).
// ---------------------------------------------------------------------------
__global__ void __launch_bounds__(TPB, 7) pool_partial_kernel(
    const float* __restrict__ hs,
    const int* __restrict__ plens,
    const int* __restrict__ ilens,
    int D)
{
    // Reset finalize counters for this replay (only kernel 2 reads them).
    if (blockIdx.x == 0 && blockIdx.y == 0 && blockIdx.z == 0 &&
        threadIdx.x < 64)
        g_cnt[threadIdx.x] = 0;

    const int b     = blockIdx.x;
    const int chunk = blockIdx.y;
    const int dblk  = blockIdx.z;

    long start = 0;
    for (int i = 0; i < b; ++i) start += plens[i];

    const int pl = plens[b];
    const int il = ilens[b];
    const int n  = pl - il;  // valid token count

    const int t0 = (int)((long)chunk * n / CHUNKS);
    const int t1 = (int)((long)(chunk + 1) * n / CHUNKS);

    const int col = dblk * (TPB * 4) + threadIdx.x * 4;
    if (col >= D) return;

    const float* base = hs + (start + il) * (long)D + col;

    float4 acc0 = make_float4(0.f, 0.f, 0.f, 0.f);
    float4 acc1 = make_float4(0.f, 0.f, 0.f, 0.f);

    int t = t0;
    for (; t + 4 <= t1; t += 4) {
        float4 v0 = __ldcs((const float4*)(base + (long)(t + 0) * D));
        float4 v1 = __ldcs((const float4*)(base + (long)(t + 1) * D));
        float4 v2 = __ldcs((const float4*)(base + (long)(t + 2) * D));
        float4 v3 = __ldcs((const float4*)(base + (long)(t + 3) * D));
        acc0.x += v0.x + v1.x; acc0.y += v0.y + v1.y;
        acc0.z += v0.z + v1.z; acc0.w += v0.w + v1.w;
        acc1.x += v2.x + v3.x; acc1.y += v2.y + v3.y;
        acc1.z += v2.z + v3.z; acc1.w += v2.w + v3.w;
    }
    for (; t < t1; ++t) {
        float4 v = __ldcs((const float4*)(base + (long)t * D));
        acc0.x += v.x; acc0.y += v.y; acc0.z += v.z; acc0.w += v.w;
    }
    acc0.x += acc1.x; acc0.y += acc1.y; acc0.z += acc1.z; acc0.w += acc1.w;

    float* out = g_partial + ((long)b * CHUNKS + chunk) * D + col;
    *(float4*)out = acc0;
}

// ---------------------------------------------------------------------------
// Kernel 2: reduce chunks -> mean (registers), spin-sync per sequence on a
// counter, deterministic fixed-order norm, normalize, write output.
// grid = (B, FBLK) = 128 blocks (one per SM, all co-resident -> spin safe).
// ---------------------------------------------------------------------------
__global__ void __launch_bounds__(FTPB) pool_finalize_kernel(
    const int* __restrict__ plens,
    const int* __restrict__ ilens,
    float* __restrict__ out,
    int D)
{
    const int b    = blockIdx.x;
    const int cblk = blockIdx.y;
    const int cnt  = plens[b] - ilens[b];
    const float inv = 1.0f / (float)cnt;

    const int col = cblk * (FTPB * 4) + threadIdx.x * 4;

    float4 mean = make_float4(0.f, 0.f, 0.f, 0.f);
    float ss_local = 0.f;

    if (col < D) {
        const float* pb = g_partial + (long)b * CHUNKS * D + col;
        float4 s0 = make_float4(0.f, 0.f, 0.f, 0.f);
        float4 s1 = make_float4(0.f, 0.f, 0.f, 0.f);
        #pragma unroll
        for (int ch = 0; ch < CHUNKS; ch += 2) {
            float4 v = __ldg((const float4*)(pb + (long)ch * D));
            float4 w = __ldg((const float4*)(pb + (long)(ch + 1) * D));
            s0.x += v.x; s0.y += v.y; s0.z += v.z; s0.w += v.w;
            s1.x += w.x; s1.y += w.y; s1.z += w.z; s1.w += w.w;
        }
        mean.x = (s0.x + s1.x) * inv;
        mean.y = (s0.y + s1.y) * inv;
        mean.z = (s0.z + s1.z) * inv;
        mean.w = (s0.w + s1.w) * inv;
        ss_local = mean.x * mean.x + mean.y * mean.y +
                   mean.z * mean.z + mean.w * mean.w;
    }

    // Block reduction of ss_local (4 warps).
    __shared__ float red[FTPB / 32];
    unsigned mask = 0xFFFFFFFFu;
    float ss = ss_local;
    #pragma unroll
    for (int off = 16; off > 0; off >>= 1)
        ss += __shfl_xor_sync(mask, ss, off);
    const int lane = threadIdx.x & 31;
    const int wid  = threadIdx.x >> 5;
    if (lane == 0) red[wid] = ss;
    __syncthreads();
    if (threadIdx.x == 0) {
        float v = red[0] + red[1] + red[2] + red[3];
        g_ss[b * FBLK + cblk] = v;
        __threadfence();
        atomicAdd(&g_cnt[b], 1);
        while (*(volatile int*)&g_cnt[b] < FBLK) { }
    }
    __syncthreads();
    __threadfence();  // acquire: make peer g_ss writes visible

    // Deterministic fixed-order sum of the FBLK partials.
    float total = 0.f;
    #pragma unroll
    for (int i = 0; i < FBLK; ++i)
        total += *(volatile float*)&g_ss[b * FBLK + i];

    float norm = fmaxf(sqrtf(total), 1e-12f);
    const float r = 1.0f / norm;

    if (col < D) {
        mean.x *= r; mean.y *= r; mean.z *= r; mean.w *= r;
        *(float4*)(out + (long)b * D + col) = mean;
    }
}

// ---------------------------------------------------------------------------
extern "C" void kernel_launch(void* const* d_in, const int* in_sizes, int n_in,
                              void* d_out, int out_size)
{
    const float* hs    = (const float*)d_in[0];
    const int*   plens = (const int*)d_in[1];
    const int*   ilens = (const int*)d_in[2];
    float*       out   = (float*)d_out;

    const int B = in_sizes[1];
    const int D = out_size / B;

    const int dblocks = (D + TPB * 4 - 1) / (TPB * 4);   // 1024 cols per block

    dim3 grid1(B, CHUNKS, dblocks);
    pool_partial_kernel<<<grid1, TPB>>>(hs, plens, ilens, D);

    const int fblocks = (D + FTPB * 4 - 1) / (FTPB * 4); // 512 cols per block
    dim3 grid2(B, fblocks);
    pool_finalize_kernel<<<grid2, FTPB>>>(plens, ilens, out, D);
}

// round 8
// speedup vs baseline: 1.0468x; 1.0048x over previous
#include <cuda_runtime.h>

#define CHUNKS 16
#define TPB 256
#define MAXB 64

// Scratch: partial sums [B, CHUNKS, D]. 16 MB static (needs 4 MB here).
__device__ float g_partial[1 << 22];
__device__ float g_ss[MAXB * 8];    // per-(b, dblk) squared-norm partials
__device__ int   g_cnt[MAXB];       // partial-completion counters (target CHUNKS*dblks)
__device__ int   g_nc[MAXB];        // ss-publication counters (target dblks)
__device__ int   g_fin[MAXB];       // finalize-exit counters (for reset)
// All zero-initialized at module load; reset to 0 by last finalize block each replay.

__global__ void __launch_bounds__(TPB, 7) pool_fused_kernel(
    const float* __restrict__ hs,
    const int* __restrict__ plens,
    const int* __restrict__ ilens,
    float* __restrict__ out,
    int D, int dblks)
{
    const int b     = blockIdx.x;
    const int chunk = blockIdx.y;
    const int dblk  = blockIdx.z;

    long start = 0;
    for (int i = 0; i < b; ++i) start += plens[i];

    const int pl = plens[b];
    const int il = ilens[b];
    const int n  = pl - il;  // valid token count

    const int t0 = (int)((long)chunk * n / CHUNKS);
    const int t1 = (int)((long)(chunk + 1) * n / CHUNKS);

    const int col = dblk * (TPB * 4) + threadIdx.x * 4;
    const bool colOK = (col < D);

    // ---------------- Phase 1: streaming partial sum --------------------
    if (colOK) {
        const float* base = hs + (start + il) * (long)D + col;

        float4 acc0 = make_float4(0.f, 0.f, 0.f, 0.f);
        float4 acc1 = make_float4(0.f, 0.f, 0.f, 0.f);

        int t = t0;
        for (; t + 4 <= t1; t += 4) {
            float4 v0 = __ldcs((const float4*)(base + (long)(t + 0) * D));
            float4 v1 = __ldcs((const float4*)(base + (long)(t + 1) * D));
            float4 v2 = __ldcs((const float4*)(base + (long)(t + 2) * D));
            float4 v3 = __ldcs((const float4*)(base + (long)(t + 3) * D));
            acc0.x += v0.x + v1.x; acc0.y += v0.y + v1.y;
            acc0.z += v0.z + v1.z; acc0.w += v0.w + v1.w;
            acc1.x += v2.x + v3.x; acc1.y += v2.y + v3.y;
            acc1.z += v2.z + v3.z; acc1.w += v2.w + v3.w;
        }
        for (; t < t1; ++t) {
            float4 v = __ldcs((const float4*)(base + (long)t * D));
            acc0.x += v.x; acc0.y += v.y; acc0.z += v.z; acc0.w += v.w;
        }
        acc0.x += acc1.x; acc0.y += acc1.y;
        acc0.z += acc1.z; acc0.w += acc1.w;

        float* o = g_partial + ((long)b * CHUNKS + chunk) * D + col;
        *(float4*)o = acc0;
    }

    // Publish completion of this partial block.
    __syncthreads();
    __threadfence();
    if (threadIdx.x == 0)
        atomicAdd(&g_cnt[b], 1);

    // ---------------- Phase 2: finalize (chunk==0 blocks only) ----------
    if (chunk != 0) return;

    const int target = CHUNKS * dblks;
    if (threadIdx.x == 0) {
        while (*(volatile int*)&g_cnt[b] != target) __nanosleep(64);
    }
    __syncthreads();

    const float inv = 1.0f / (float)n;
    float4 mean = make_float4(0.f, 0.f, 0.f, 0.f);
    float ss_local = 0.f;

    if (colOK) {
        const float* pb = g_partial + (long)b * CHUNKS * D + col;
        float4 s0 = make_float4(0.f, 0.f, 0.f, 0.f);
        float4 s1 = make_float4(0.f, 0.f, 0.f, 0.f);
        #pragma unroll
        for (int ch = 0; ch < CHUNKS; ch += 2) {
            float4 v = __ldcg((const float4*)(pb + (long)ch * D));
            float4 w = __ldcg((const float4*)(pb + (long)(ch + 1) * D));
            s0.x += v.x; s0.y += v.y; s0.z += v.z; s0.w += v.w;
            s1.x += w.x; s1.y += w.y; s1.z += w.z; s1.w += w.w;
        }
        mean.x = (s0.x + s1.x) * inv;
        mean.y = (s0.y + s1.y) * inv;
        mean.z = (s0.z + s1.z) * inv;
        mean.w = (s0.w + s1.w) * inv;
        ss_local = mean.x * mean.x + mean.y * mean.y +
                   mean.z * mean.z + mean.w * mean.w;
    }

    // Block reduction of ss_local (8 warps).
    __shared__ float red[TPB / 32];
    unsigned mask = 0xFFFFFFFFu;
    float ss = ss_local;
    #pragma unroll
    for (int off = 16; off > 0; off >>= 1)
        ss += __shfl_xor_sync(mask, ss, off);
    const int lane = threadIdx.x & 31;
    const int wid  = threadIdx.x >> 5;
    if (lane == 0) red[wid] = ss;
    __syncthreads();

    if (threadIdx.x == 0) {
        float v = 0.f;
        #pragma unroll
        for (int i = 0; i < TPB / 32; ++i) v += red[i];
        g_ss[b * 8 + dblk] = v;
        __threadfence();
        atomicAdd(&g_nc[b], 1);
        while (*(volatile int*)&g_nc[b] != dblks) __nanosleep(32);
    }
    __syncthreads();

    // Deterministic fixed-order sum of the per-dblk partials.
    float total = 0.f;
    for (int i = 0; i < dblks; ++i)
        total += *(volatile float*)&g_ss[b * 8 + i];

    const float r = 1.0f / fmaxf(sqrtf(total), 1e-12f);

    if (colOK) {
        mean.x *= r; mean.y *= r; mean.z *= r; mean.w *= r;
        *(float4*)(out + (long)b * D + col) = mean;
    }

    // Reset counters for the next replay: last finalize block of b does it.
    __syncthreads();
    if (threadIdx.x == 0) {
        int old = atomicAdd(&g_fin[b], 1);
        if (old == dblks - 1) {
            g_cnt[b] = 0;
            g_nc[b]  = 0;
            g_fin[b] = 0;
            __threadfence();
        }
    }
}

// ---------------------------------------------------------------------------
extern "C" void kernel_launch(void* const* d_in, const int* in_sizes, int n_in,
                              void* d_out, int out_size)
{
    const float* hs    = (const float*)d_in[0];
    const int*   plens = (const int*)d_in[1];
    const int*   ilens = (const int*)d_in[2];
    float*       out   = (float*)d_out;

    const int B = in_sizes[1];
    const int D = out_size / B;

    const int dblks = (D + TPB * 4 - 1) / (TPB * 4);   // 1024 cols per block

    dim3 grid(B, CHUNKS, dblks);
    pool_fused_kernel<<<grid, TPB>>>(hs, plens, ilens, out, D, dblks);
}

// round 10
// speedup vs baseline: 1.0674x; 1.0197x over previous
#include <cuda_runtime.h>

#define CHUNKS 8
#define TPB 256
#define MAXB 64

// Scratch: partial sums [B, CHUNKS, D]. 16 MB static (needs 2 MB here).
__device__ float g_partial[1 << 22];
__device__ float g_ss[MAXB * 8];    // per-(b, dblk) squared-norm partials
__device__ int   g_cnt[MAXB];       // partial-completion counters (target CHUNKS*dblks)
__device__ int   g_nc[MAXB];        // ss-publication counters (target dblks)
__device__ int   g_fin[MAXB];       // finalize-exit counters (for reset)
// Zero-initialized at load; reset by the last finalize block of each sequence
// every replay, so the kernel is replay-safe under graph capture.

__global__ void __launch_bounds__(TPB) pool_fused_kernel(
    const float* __restrict__ hs,
    const int* __restrict__ plens,
    const int* __restrict__ ilens,
    float* __restrict__ out,
    int D, int dblks)
{
    const int b     = blockIdx.x;
    const int chunk = blockIdx.y;
    const int dblk  = blockIdx.z;

    long start = 0;
    for (int i = 0; i < b; ++i) start += plens[i];

    const int pl = plens[b];
    const int il = ilens[b];
    const int n  = pl - il;  // valid token count

    const int t0 = (int)((long)chunk * n / CHUNKS);
    const int t1 = (int)((long)(chunk + 1) * n / CHUNKS);

    const int col = dblk * (TPB * 4) + threadIdx.x * 4;
    const bool colOK = (col < D);

    // ---------------- Phase 1: streaming partial sum (R2 loop) ----------
    if (colOK) {
        const float* base = hs + (start + il) * (long)D + col;

        float4 acc0 = make_float4(0.f, 0.f, 0.f, 0.f);
        float4 acc1 = make_float4(0.f, 0.f, 0.f, 0.f);

        int t = t0;
        // 8 independent streaming LDG.128 per iteration for deep MLP.
        for (; t + 8 <= t1; t += 8) {
            float4 v0 = __ldcs((const float4*)(base + (long)(t + 0) * D));
            float4 v1 = __ldcs((const float4*)(base + (long)(t + 1) * D));
            float4 v2 = __ldcs((const float4*)(base + (long)(t + 2) * D));
            float4 v3 = __ldcs((const float4*)(base + (long)(t + 3) * D));
            float4 v4 = __ldcs((const float4*)(base + (long)(t + 4) * D));
            float4 v5 = __ldcs((const float4*)(base + (long)(t + 5) * D));
            float4 v6 = __ldcs((const float4*)(base + (long)(t + 6) * D));
            float4 v7 = __ldcs((const float4*)(base + (long)(t + 7) * D));
            acc0.x += (v0.x + v1.x) + (v2.x + v3.x);
            acc0.y += (v0.y + v1.y) + (v2.y + v3.y);
            acc0.z += (v0.z + v1.z) + (v2.z + v3.z);
            acc0.w += (v0.w + v1.w) + (v2.w + v3.w);
            acc1.x += (v4.x + v5.x) + (v6.x + v7.x);
            acc1.y += (v4.y + v5.y) + (v6.y + v7.y);
            acc1.z += (v4.z + v5.z) + (v6.z + v7.z);
            acc1.w += (v4.w + v5.w) + (v6.w + v7.w);
        }
        for (; t < t1; ++t) {
            float4 v = __ldcs((const float4*)(base + (long)t * D));
            acc0.x += v.x; acc0.y += v.y; acc0.z += v.z; acc0.w += v.w;
        }
        acc0.x += acc1.x; acc0.y += acc1.y;
        acc0.z += acc1.z; acc0.w += acc1.w;

        float* o = g_partial + ((long)b * CHUNKS + chunk) * D + col;
        *(float4*)o = acc0;
    }

    // Publish completion of this partial block.
    __syncthreads();
    __threadfence();
    if (threadIdx.x == 0)
        atomicAdd(&g_cnt[b], 1);

    // ---------------- Phase 2: finalize (chunk==0 blocks only) ----------
    if (chunk != 0) return;

    const int target = CHUNKS * dblks;
    if (threadIdx.x == 0) {
        while (*(volatile int*)&g_cnt[b] != target) __nanosleep(64);
    }
    __syncthreads();

    const float inv = 1.0f / (float)n;
    float4 mean = make_float4(0.f, 0.f, 0.f, 0.f);
    float ss_local = 0.f;

    if (colOK) {
        const float* pb = g_partial + (long)b * CHUNKS * D + col;
        float4 s0 = make_float4(0.f, 0.f, 0.f, 0.f);
        float4 s1 = make_float4(0.f, 0.f, 0.f, 0.f);
        #pragma unroll
        for (int ch = 0; ch < CHUNKS; ch += 2) {
            float4 v = __ldcg((const float4*)(pb + (long)ch * D));
            float4 w = __ldcg((const float4*)(pb + (long)(ch + 1) * D));
            s0.x += v.x; s0.y += v.y; s0.z += v.z; s0.w += v.w;
            s1.x += w.x; s1.y += w.y; s1.z += w.z; s1.w += w.w;
        }
        mean.x = (s0.x + s1.x) * inv;
        mean.y = (s0.y + s1.y) * inv;
        mean.z = (s0.z + s1.z) * inv;
        mean.w = (s0.w + s1.w) * inv;
        ss_local = mean.x * mean.x + mean.y * mean.y +
                   mean.z * mean.z + mean.w * mean.w;
    }

    // Block reduction of ss_local (8 warps).
    __shared__ float red[TPB / 32];
    unsigned mask = 0xFFFFFFFFu;
    float ss = ss_local;
    #pragma unroll
    for (int off = 16; off > 0; off >>= 1)
        ss += __shfl_xor_sync(mask, ss, off);
    const int lane = threadIdx.x & 31;
    const int wid  = threadIdx.x >> 5;
    if (lane == 0) red[wid] = ss;
    __syncthreads();

    if (threadIdx.x == 0) {
        float v = 0.f;
        #pragma unroll
        for (int i = 0; i < TPB / 32; ++i) v += red[i];
        g_ss[b * 8 + dblk] = v;
        __threadfence();
        atomicAdd(&g_nc[b], 1);
        while (*(volatile int*)&g_nc[b] != dblks) __nanosleep(32);
    }
    __syncthreads();

    // Deterministic fixed-order sum of the per-dblk partials.
    float total = 0.f;
    for (int i = 0; i < dblks; ++i)
        total += *(volatile float*)&g_ss[b * 8 + i];

    const float r = 1.0f / fmaxf(sqrtf(total), 1e-12f);

    if (colOK) {
        mean.x *= r; mean.y *= r; mean.z *= r; mean.w *= r;
        *(float4*)(out + (long)b * D + col) = mean;
    }

    // Reset counters for the next replay: last finalize block of b does it.
    __syncthreads();
    if (threadIdx.x == 0) {
        int old = atomicAdd(&g_fin[b], 1);
        if (old == dblks - 1) {
            g_cnt[b] = 0;
            g_nc[b]  = 0;
            g_fin[b] = 0;
            __threadfence();
        }
    }
}

// ---------------------------------------------------------------------------
extern "C" void kernel_launch(void* const* d_in, const int* in_sizes, int n_in,
                              void* d_out, int out_size)
{
    const float* hs    = (const float*)d_in[0];
    const int*   plens = (const int*)d_in[1];
    const int*   ilens = (const int*)d_in[2];
    float*       out   = (float*)d_out;

    const int B = in_sizes[1];
    const int D = out_size / B;

    const int dblks = (D + TPB * 4 - 1) / (TPB * 4);   // 1024 cols per block

    dim3 grid(B, CHUNKS, dblks);
    pool_fused_kernel<<<grid, TPB>>>(hs, plens, ilens, out, D, dblks);
}